// round 1
// baseline (speedup 1.0000x reference)
#include <cuda_runtime.h>

// Problem: B=512 rows, L=16 labels, N = B*L = 8192 flattened yp values.
// loss = sum_l inv[l] * sum_{p,q} yt[row(p),l] * (1-yt[row(q),l]) * relu(1 - x_p + x_q)
// Sorted-x + per-label suffix sums turn the q-sum into one table lookup + FMA.

#define NTOT 8192
#define NROW 512
#define NL   16
#define NTHR 1024
#define EPT  (NTOT / NTHR)   // elements per thread = 8

__device__ float           g_x[NTOT];       // sorted yp values (ascending)
__device__ unsigned short  g_srow[NTOT];    // original row of each sorted element
__device__ float           g_inv[NL];       // 1/((np*nn)^2 * L^2) or 0 if invalid
__device__ float           g_SB [NL][NTOT]; // suffix sum of (1 - yt[row,l])
__device__ float           g_SBX[NL][NTOT]; // suffix sum of (1 - yt[row,l]) * x
__device__ float           g_part[NTOT / 256];

// ---------------------------------------------------------------------------
// Kernel 1: single CTA — per-label stats + bitonic sort of all 8192 values
// (value, original-row) pairs sorted ascending by value.
// ---------------------------------------------------------------------------
__global__ void k_sort(const int* __restrict__ yt, const float* __restrict__ yp) {
    extern __shared__ char smraw[];
    float*          xs = (float*)smraw;
    unsigned short* rs = (unsigned short*)(smraw + NTOT * sizeof(float));
    const int tid = threadIdx.x;

    #pragma unroll
    for (int e = 0; e < EPT; e++) {
        int i = tid + e * NTHR;
        xs[i] = yp[i];
        rs[i] = (unsigned short)(i >> 4);   // row = flat_index / 16
    }

    // Per-label n_pos / n_neg / inverse denominator (threads 0..15)
    if (tid < NL) {
        int np = 0;
        #pragma unroll 8
        for (int r = 0; r < NROW; r++) np += yt[r * NL + tid];
        int nn = NROW - np;
        double d = (double)np * (double)nn;
        g_inv[tid] = (np > 0 && nn > 0)
                   ? (float)(1.0 / (d * d * (double)(NL * NL)))
                   : 0.0f;
    }
    __syncthreads();

    // Bitonic sort, ascending. Each (k,j) pass: pairs are disjoint; the thread
    // owning the lower index of a pair performs the compare-exchange.
    for (int k = 2; k <= NTOT; k <<= 1) {
        for (int j = k >> 1; j > 0; j >>= 1) {
            #pragma unroll
            for (int e = 0; e < EPT; e++) {
                int i   = tid + e * NTHR;
                int ixj = i ^ j;
                if (ixj > i) {
                    bool up = ((i & k) == 0);
                    float a = xs[i], b = xs[ixj];
                    if ((a > b) == up) {
                        xs[i] = b; xs[ixj] = a;
                        unsigned short t = rs[i]; rs[i] = rs[ixj]; rs[ixj] = t;
                    }
                }
            }
            __syncthreads();
        }
    }

    #pragma unroll
    for (int e = 0; e < EPT; e++) {
        int i = tid + e * NTHR;
        g_x[i]    = xs[i];
        g_srow[i] = rs[i];
    }
}

// ---------------------------------------------------------------------------
// Kernel 2: one block per label — inclusive SUFFIX scans of beta and beta*x
// over the sorted order (Hillis-Steele, in shared memory).
// SB counts are integer-valued tree sums < 2^24 -> exact in fp32.
// ---------------------------------------------------------------------------
__global__ void k_scan(const int* __restrict__ yt) {
    extern __shared__ float s[];
    float* b  = s;          // [NTOT]
    float* bx = s + NTOT;   // [NTOT]
    const int l   = blockIdx.x;
    const int tid = threadIdx.x;

    #pragma unroll
    for (int e = 0; e < EPT; e++) {
        int i = tid + e * NTHR;
        float beta = yt[(int)g_srow[i] * NL + l] ? 0.0f : 1.0f;
        b[i]  = beta;
        bx[i] = beta * g_x[i];
    }
    __syncthreads();

    for (int off = 1; off < NTOT; off <<= 1) {
        float vb[EPT], vx[EPT];
        #pragma unroll
        for (int e = 0; e < EPT; e++) {
            int i = tid + e * NTHR;
            int j = i + off;
            vb[e] = (j < NTOT) ? b[j]  : 0.0f;
            vx[e] = (j < NTOT) ? bx[j] : 0.0f;
        }
        __syncthreads();
        #pragma unroll
        for (int e = 0; e < EPT; e++) {
            int i = tid + e * NTHR;
            b[i]  += vb[e];
            bx[i] += vx[e];
        }
        __syncthreads();
    }

    #pragma unroll
    for (int e = 0; e < EPT; e++) {
        int i = tid + e * NTHR;
        g_SB [l][i] = b[i];
        g_SBX[l][i] = bx[i];
    }
}

// ---------------------------------------------------------------------------
// Kernel 3: per sorted element p — binary search for the relu cutoff, then
// 16 label contributions via one table FMA each. Tree-reduce per block.
// ---------------------------------------------------------------------------
__global__ void k_loss(const int* __restrict__ yt) {
    const int p = blockIdx.x * blockDim.x + threadIdx.x;
    float xp  = g_x[p];
    float thr = xp - 1.0f;   // include q iff x_q >= x_p - 1 (equality adds 0)

    int lo = 0, hi = NTOT;
    while (lo < hi) {
        int mid = (lo + hi) >> 1;
        if (g_x[mid] < thr) lo = mid + 1; else hi = mid;
    }

    float acc = 0.0f;
    if (lo < NTOT) {
        int   row = (int)g_srow[p];
        float a1  = 1.0f - xp;
        #pragma unroll
        for (int l = 0; l < NL; l++) {
            if (yt[row * NL + l]) {
                acc += g_inv[l] * fmaf(a1, g_SB[l][lo], g_SBX[l][lo]);
            }
        }
    }

    __shared__ float red[256];
    red[threadIdx.x] = acc;
    __syncthreads();
    for (int s2 = 128; s2 > 0; s2 >>= 1) {
        if (threadIdx.x < s2) red[threadIdx.x] += red[threadIdx.x + s2];
        __syncthreads();
    }
    if (threadIdx.x == 0) g_part[blockIdx.x] = red[0];
}

// ---------------------------------------------------------------------------
// Kernel 4: final reduction of 32 partials -> d_out[0]
// ---------------------------------------------------------------------------
__global__ void k_final(float* __restrict__ out, int n) {
    float v = g_part[threadIdx.x];
    #pragma unroll
    for (int s = 16; s > 0; s >>= 1) v += __shfl_down_sync(0xffffffffu, v, s);
    v = __shfl_sync(0xffffffffu, v, 0);
    for (int i = threadIdx.x; i < n; i += 32) out[i] = (i == 0) ? v : 0.0f;
}

extern "C" void kernel_launch(void* const* d_in, const int* in_sizes, int n_in,
                              void* d_out, int out_size) {
    const int*   yt  = (const int*)d_in[0];    // y_true int32 [512*16]
    const float* yp  = (const float*)d_in[1];  // y_pred fp32  [512*16]
    float*       out = (float*)d_out;

    // Opt-in shared memory (k_sort 48KB, k_scan 64KB). Attribute set is
    // idempotent and not a stream op — safe under graph capture.
    cudaFuncSetAttribute(k_sort, cudaFuncAttributeMaxDynamicSharedMemorySize, 64 * 1024);
    cudaFuncSetAttribute(k_scan, cudaFuncAttributeMaxDynamicSharedMemorySize, 72 * 1024);

    k_sort <<<1, NTHR, NTOT * (sizeof(float) + sizeof(unsigned short))>>>(yt, yp);
    k_scan <<<NL, NTHR, 2 * NTOT * sizeof(float)>>>(yt);
    k_loss <<<NTOT / 256, 256>>>(yt);
    k_final<<<1, 32>>>(out, out_size);
}

// round 2
// speedup vs baseline: 7.5455x; 7.5455x over previous
#include <cuda_runtime.h>

// B=512 rows, L=16 labels, N=8192 values.
// loss = sum_{i,j} W[i,j] * S[i,j]
//   W[i,j] = sum_l inv[l] * [yt[i,l]==1] * [yt[j,l]==0],  inv[l]=1/((np*nn)^2 L^2)
//   S[i,j] = sum_{c,d} relu(1 - x[i,c] + x[j,d])
//          = 0.5 * ( sum|t| + 256 - 16*sx[i] + 16*sx[j] )   [relu(t)=(t+|t|)/2, exact]
// Inner loop accumulates only sum|t| with packed f32x2 adds.

#define NROW 512
#define NL   16
#define TI   16
#define TJ   16
#define GB   (NROW / TI)          // 32 blocks per grid dim
#define NPART (GB * GB)           // 1024 partials

__device__ unsigned int g_pm[NROW];   // 16-bit positive mask per row
__device__ float        g_sx[NROW];   // per-row sum of yp
__device__ float        g_tlo[256];   // sum of inv[l], l<8, over bits of index
__device__ float        g_thi[256];   // sum of inv[8+l] over bits of index
__device__ float        g_part[NPART];

// ---- packed f32x2 helpers -------------------------------------------------
__device__ __forceinline__ unsigned long long pk2(float lo, float hi) {
    unsigned long long r;
    asm("mov.b64 %0, {%1, %2};" : "=l"(r) : "f"(lo), "f"(hi));
    return r;
}
__device__ __forceinline__ unsigned long long addx2(unsigned long long a,
                                                    unsigned long long b) {
    unsigned long long r;
    asm("add.rn.f32x2 %0, %1, %2;" : "=l"(r) : "l"(a), "l"(b));
    return r;
}
__device__ __forceinline__ void unpk2(unsigned long long v, float& lo, float& hi) {
    asm("mov.b64 {%0, %1}, %2;" : "=f"(lo), "=f"(hi) : "l"(v));
}

// ---------------------------------------------------------------------------
// Setup: one block, 512 threads. Per-row masks + sums, label counts via
// ballots, inverse denominators, and the two 256-entry weight tables.
// ---------------------------------------------------------------------------
__global__ void k_setup(const int* __restrict__ yt, const float* __restrict__ yp) {
    __shared__ int   cnt[NL];
    __shared__ float inv_s[NL];
    const int r   = threadIdx.x;            // row, 0..511
    const int lid = r & 31;

    if (r < NL) cnt[r] = 0;
    __syncthreads();

    // Row mask + row sum (vectorized 4x float4)
    unsigned pm = 0;
    float sx = 0.0f;
    {
        const int4*   y4 = (const int4*)(yt + r * NL);
        const float4* p4 = (const float4*)(yp + r * NL);
        #pragma unroll
        for (int q = 0; q < 4; q++) {
            int4 yv = y4[q];
            if (yv.x) pm |= 1u << (4 * q + 0);
            if (yv.y) pm |= 1u << (4 * q + 1);
            if (yv.z) pm |= 1u << (4 * q + 2);
            if (yv.w) pm |= 1u << (4 * q + 3);
            float4 pv = p4[q];
            sx += (pv.x + pv.y) + (pv.z + pv.w);
        }
    }
    g_pm[r] = pm;
    g_sx[r] = sx;

    // n_pos per label via warp ballots
    #pragma unroll
    for (int l = 0; l < NL; l++) {
        unsigned b = __ballot_sync(0xffffffffu, (pm >> l) & 1u);
        if (lid == 0) atomicAdd(&cnt[l], __popc(b));
    }
    __syncthreads();

    if (r < NL) {
        int np = cnt[r], nn = NROW - np;
        double d = (double)np * (double)nn;
        inv_s[r] = (np > 0 && nn > 0)
                 ? (float)(1.0 / (d * d * (double)(NL * NL)))
                 : 0.0f;
    }
    __syncthreads();

    // Weight tables: tlo[m] = sum_{l<8, bit l of m} inv[l]; thi for high bits
    if (r < 256) {
        float lo = 0.0f, hi = 0.0f;
        #pragma unroll
        for (int l = 0; l < 8; l++) {
            if ((r >> l) & 1) { lo += inv_s[l]; hi += inv_s[8 + l]; }
        }
        g_tlo[r] = lo;
        g_thi[r] = hi;
    }
}

// ---------------------------------------------------------------------------
// Main: grid 32x32, block 256 (one thread per (i,j) row pair in a 16x16 tile).
// Inner loop: 128 packed f32x2 units = 256 element pairs per thread.
// ---------------------------------------------------------------------------
__global__ void __launch_bounds__(256) k_main(const float* __restrict__ yp) {
    __shared__ float xi[TI * NL], xj[TJ * NL];
    __shared__ float tlo_s[256], thi_s[256];
    __shared__ unsigned pmI[TI], nmJ[TJ];
    __shared__ float sxI[TI], sxJ[TJ];

    const int bi  = blockIdx.x, bj = blockIdx.y;
    const int tid = threadIdx.x;

    xi[tid]    = yp[bi * TI * NL + tid];
    xj[tid]    = yp[bj * TJ * NL + tid];
    tlo_s[tid] = g_tlo[tid];
    thi_s[tid] = g_thi[tid];
    if (tid < TI) {
        pmI[tid] = g_pm[bi * TI + tid];
        sxI[tid] = g_sx[bi * TI + tid];
    } else if (tid < TI + TJ) {
        int j = tid - TI;
        nmJ[j] = (~g_pm[bj * TJ + j]) & 0xFFFFu;
        sxJ[j] = g_sx[bj * TJ + j];
    }
    __syncthreads();

    const int il = tid >> 4;
    const int jl = tid & 15;

    // ci2[k] = { 1 - xi[il][2k], 1 - xi[il][2k+1] }
    unsigned long long ci2[8];
    #pragma unroll
    for (int k = 0; k < 8; k++)
        ci2[k] = pk2(1.0f - xi[il * NL + 2 * k], 1.0f - xi[il * NL + 2 * k + 1]);

    const unsigned long long ABSM = 0x7FFFFFFF7FFFFFFFULL;
    unsigned long long sa0 = 0, sa1 = 0;   // two accumulators to break the chain

    #pragma unroll
    for (int d = 0; d < NL; d++) {
        float xq = xj[jl * NL + d];
        unsigned long long xq2 = pk2(xq, xq);
        #pragma unroll
        for (int k = 0; k < 8; k += 2) {
            unsigned long long t0 = addx2(ci2[k],     xq2) & ABSM;
            unsigned long long t1 = addx2(ci2[k + 1], xq2) & ABSM;
            sa0 = addx2(sa0, t0);
            sa1 = addx2(sa1, t1);
        }
    }

    float a0, a1, b0, b1;
    unpk2(sa0, a0, a1);
    unpk2(sa1, b0, b1);
    float s_abs = (a0 + a1) + (b0 + b1);
    float sum_t = 256.0f - 16.0f * sxI[il] + 16.0f * sxJ[jl];

    unsigned mask = pmI[il] & nmJ[jl];
    float W = tlo_s[mask & 255u] + thi_s[mask >> 8];
    float contrib = W * 0.5f * (s_abs + sum_t);

    // Deterministic block tree reduction
    __shared__ float red[256];
    red[tid] = contrib;
    __syncthreads();
    #pragma unroll
    for (int s = 128; s > 0; s >>= 1) {
        if (tid < s) red[tid] += red[tid + s];
        __syncthreads();
    }
    if (tid == 0) g_part[bj * GB + bi] = red[0];
}

// ---------------------------------------------------------------------------
// Final: reduce 1024 partials -> out[0]; zero the rest of out.
// ---------------------------------------------------------------------------
__global__ void k_final(float* __restrict__ out, int n) {
    const int tid = threadIdx.x;   // 256
    float v = g_part[tid] + g_part[tid + 256] + g_part[tid + 512] + g_part[tid + 768];
    __shared__ float red[256];
    red[tid] = v;
    __syncthreads();
    #pragma unroll
    for (int s = 128; s > 0; s >>= 1) {
        if (tid < s) red[tid] += red[tid + s];
        __syncthreads();
    }
    for (int i = tid; i < n; i += 256) out[i] = (i == 0) ? red[0] : 0.0f;
}

extern "C" void kernel_launch(void* const* d_in, const int* in_sizes, int n_in,
                              void* d_out, int out_size) {
    const int*   yt  = (const int*)d_in[0];    // y_true int32 [512*16]
    const float* yp  = (const float*)d_in[1];  // y_pred fp32  [512*16]
    float*       out = (float*)d_out;

    k_setup<<<1, NROW>>>(yt, yp);
    dim3 grid(GB, GB);
    k_main<<<grid, 256>>>(yp);
    k_final<<<1, 256>>>(out, out_size);
}